// round 3
// baseline (speedup 1.0000x reference)
#include <cuda_runtime.h>
#include <cstdint>
#include <cub/block/block_radix_sort.cuh>

// CutOutput: per-row (P*T = 8192 rows) stable descending argsort of D=1571
// fp32 scores; output[row][r] = index at rank r if r < len else 0, with
// len = base[row] (ids = repeat(arange(P), T) makes visit (p,t) <-> row p*T+t).
//
// KEY FIX this round: harness __output__ dtype is float32 (both prior rounds,
// with two independent correct-ish sorts, returned rel_err == 1.0 exactly ==
// "output reads as zero" == int bit patterns seen as float denormals).
// We now write (float)index.
//
//  * cub::BlockRadixSort (stable LSD radix): blocked order == index order, so
//    stability == ascending-index tie-break == JAX stable argsort.
//  * Key: monotone-descending 32-bit transform of float bits; padding = 0xFFFFFFFF
//    (unreachable for finite floats) sorts strictly last.
//  * base vs ids disambiguated on-device: ids[0]==0 always, base[0]>=1 always.

static constexpr int D = 1571;
static constexpr int THREADS = 256;
static constexpr int ITEMS = 7;            // 256*7 = 1792 >= 1571

__global__ void __launch_bounds__(THREADS) cutoutput_radix_kernel(
    const float* __restrict__ to_cut,
    const int* __restrict__ candA,
    const int* __restrict__ candB,
    float* __restrict__ out) {
  using Sorter =
      cub::BlockRadixSort<unsigned int, THREADS, ITEMS, unsigned short>;
  __shared__ typename Sorter::TempStorage tmp;

  const int row = blockIdx.x;
  const float* __restrict__ src = to_cut + (size_t)row * D;
  const int t = threadIdx.x;

  unsigned int keys[ITEMS];
  unsigned short vals[ITEMS];

  // Blocked load: thread t owns original positions [t*ITEMS, t*ITEMS+ITEMS).
#pragma unroll
  for (int i = 0; i < ITEMS; ++i) {
    const int v = t * ITEMS + i;
    unsigned int kk = 0xFFFFFFFFu;
    if (v < D) {
      const unsigned int u = __float_as_uint(src[v]);
      const unsigned int a =
          u ^ ((u & 0x80000000u) ? 0xFFFFFFFFu : 0x80000000u);
      kk = ~a;  // ascending kk == descending float value
    }
    keys[i] = kk;
    vals[i] = (unsigned short)v;
  }

  Sorter(tmp).SortBlockedToStriped(keys, vals);

  // ids[0] == 0 always; base[0] >= 1 always.
  const int* __restrict__ basep = (candA[0] == 0) ? candB : candA;
  const int len = basep[row];

  // Striped output: item i of thread t holds rank r = i*THREADS + t -> coalesced.
  float* __restrict__ dst = out + (size_t)row * D;
#pragma unroll
  for (int i = 0; i < ITEMS; ++i) {
    const int r = i * THREADS + t;
    if (r < D) dst[r] = (r < len) ? (float)vals[i] : 0.0f;
  }
}

extern "C" void kernel_launch(void* const* d_in, const int* in_sizes, int n_in,
                              void* d_out, int out_size) {
  // to_cut is the (unique) large buffer: P*T*D elements.
  int imax = 0;
  for (int i = 1; i < n_in; ++i)
    if (in_sizes[i] > in_sizes[imax]) imax = i;
  const float* to_cut = (const float*)d_in[imax];

  int others[2], k = 0;
  for (int i = 0; i < n_in && k < 2; ++i)
    if (i != imax) others[k++] = i;
  const int* candA = (const int*)d_in[others[0]];
  const int* candB = (const int*)d_in[others[1]];

  float* out = (float*)d_out;
  const int rows = in_sizes[imax] / D;  // P*T = 8192

  cutoutput_radix_kernel<<<rows, THREADS>>>(to_cut, candA, candB, out);
}